// round 2
// baseline (speedup 1.0000x reference)
#include <cuda_runtime.h>
#include <cstdint>
#include <cstddef>

#define B_TOT  512
#define LC_    512
#define IDIM   64
#define HDIM   100
#define ODIM   64
#define TSTEPS 256
#define EPB    4
#define NBLK   (B_TOT/EPB)
#define NTHR   320

// Packed weights in device globals (filled by prep_kernel):
// WcP  : [jb=16][g=300][jj=4]  = W_c[g][4*jb+jj]   (W_c = W_ih @ W_embed, 300x64)
// WhhP : [kb=25][g=300][kk=4]  = W_hh[g][4*kb+kk]  (300x100)
// WprojP:[kb=25][o= 64][kk=4]  = W_proj[o][4*kb+kk](64x100)
__device__ float g_WcP   [16*300*4];
__device__ float g_WhhP  [25*300*4];
__device__ float g_WprojP[25*64*4];
__device__ float g_bc    [300];

__global__ void prep_kernel(const float* __restrict__ W_embed,
                            const float* __restrict__ b_embed,
                            const float* __restrict__ W_ih,
                            const float* __restrict__ b_ih,
                            const float* __restrict__ W_hh,
                            const float* __restrict__ W_proj) {
  int idx = blockIdx.x * 256 + threadIdx.x;
  if (idx < 19200) {                       // W_c = W_ih(300x100) @ W_embed(100x64)
    int g = idx >> 6, j = idx & 63;
    float acc = 0.f;
    #pragma unroll 4
    for (int k = 0; k < 100; k++) acc += W_ih[g*100+k] * W_embed[k*64+j];
    g_WcP[(j>>2)*1200 + g*4 + (j&3)] = acc;
  } else if (idx < 49200) {                // repack W_hh
    int i = idx - 19200, g = i/100, k = i%100;
    g_WhhP[(k>>2)*1200 + g*4 + (k&3)] = W_hh[g*100+k];
  } else if (idx < 55600) {                // repack W_proj
    int i = idx - 49200, o = i/100, k = i%100;
    g_WprojP[(k>>2)*256 + o*4 + (k&3)] = W_proj[o*100+k];
  } else if (idx < 55900) {                // b_c = W_ih @ b_embed + b_ih
    int g = idx - 55600;
    float acc = b_ih[g];
    for (int k = 0; k < 100; k++) acc += W_ih[g*100+k] * b_embed[k];
    g_bc[g] = acc;
  }
}

struct SmemT {
  float WcP [16*300*4];   // 76800 B
  float WhhP[25*300*4];   // 120000 B
  float xinP[64*4];       // input vec packed [j][e]
  float hP  [100*4];      // hidden packed [k][e]
  float xp  [4*300];      // x-gate preacts [e][g]
  float gh  [4*300];      // h-gate preacts [e][g]
  float bc  [300];
  float bhh [300];
  float bproj[64];
  int   len [4];
};

__device__ __forceinline__ float sigmf(float x) {
  return __fdividef(1.f, 1.f + __expf(-x));
}
__device__ __forceinline__ float tanh_fast(float x) {
  return __fdividef(2.f, 1.f + __expf(-2.f * x)) - 1.f;
}

// z[e][o] = b_proj[o] + h[e] . W_proj[o]; writes d_out and stages z into xinP
__device__ __forceinline__ void zgemm(SmemT* s, int tid, int b0, int tt,
                                      float* __restrict__ out) {
  if (tid < 256) {
    int e = tid >> 6, o = tid & 63;    // warp shares e -> hP loads broadcast
    const float4* Wp4 = reinterpret_cast<const float4*>(g_WprojP);
    float acc = s->bproj[o];
    #pragma unroll
    for (int kb = 0; kb < 25; kb++) {
      float4 w = __ldg(&Wp4[kb*64 + o]);
      acc += w.x * s->hP[(kb*4+0)*4 + e];
      acc += w.y * s->hP[(kb*4+1)*4 + e];
      acc += w.z * s->hP[(kb*4+2)*4 + e];
      acc += w.w * s->hP[(kb*4+3)*4 + e];
    }
    out[((size_t)(b0+e)*(TSTEPS+1) + tt)*ODIM + o] = acc;
    s->xinP[o*4 + e] = acc;
  }
}

__global__ __launch_bounds__(NTHR, 1)
void rnn_kernel(const float* __restrict__ ctx,
                const int*   __restrict__ lens,
                const float* __restrict__ bhh_g,
                const float* __restrict__ bproj_g,
                float*       __restrict__ out) {
  extern __shared__ char smem_raw[];
  SmemT* s = reinterpret_cast<SmemT*>(smem_raw);
  const int tid = threadIdx.x;
  const int b0  = blockIdx.x << 2;

  for (int i = tid; i < 16*300*4; i += NTHR) s->WcP[i]  = g_WcP[i];
  for (int i = tid; i < 25*300*4; i += NTHR) s->WhhP[i] = g_WhhP[i];
  if (tid < 300) { s->bc[tid] = g_bc[tid]; s->bhh[tid] = bhh_g[tid]; }
  if (tid < 64)  s->bproj[tid] = bproj_g[tid];
  if (tid < 4)   s->len[tid] = lens[b0 + tid];
  for (int i = tid; i < 400; i += NTHR) s->hP[i] = 0.f;
  __syncthreads();

  int maxlen = max(max(s->len[0], s->len[1]), max(s->len[2], s->len[3]));
  if (maxlen > LC_) maxlen = LC_;

  const float4* Wc4 = reinterpret_cast<const float4*>(s->WcP);
  const float4* Wh4 = reinterpret_cast<const float4*>(s->WhhP);
  const float4* X4  = reinterpret_cast<const float4*>(s->xinP);
  const float4* H4  = reinterpret_cast<const float4*>(s->hP);

  const int total = maxlen + TSTEPS;
  for (int step = 0; step < total; step++) {
    if (step < maxlen) {
      if (tid < 256) {                       // stage ctx[:, step, :]
        int e = tid >> 6, j = tid & 63;
        s->xinP[j*4 + e] = ctx[((size_t)(b0+e)*LC_ + step)*IDIM + j];
      }
    } else {
      zgemm(s, tid, b0, step - maxlen, out); // emit z_tt, stage z as next input
    }
    __syncthreads();

    if (tid < 300) {                          // xp = xin@Wc^T+bc ; gh = h@Whh^T+bhh
      const int g = tid;
      float bcv = s->bc[g];
      float ax0 = bcv, ax1 = bcv, ax2 = bcv, ax3 = bcv;
      #pragma unroll
      for (int jb = 0; jb < 16; jb++) {
        float4 w = Wc4[jb*300 + g];
        float4 v;
        v = X4[jb*4+0]; ax0 += w.x*v.x; ax1 += w.x*v.y; ax2 += w.x*v.z; ax3 += w.x*v.w;
        v = X4[jb*4+1]; ax0 += w.y*v.x; ax1 += w.y*v.y; ax2 += w.y*v.z; ax3 += w.y*v.w;
        v = X4[jb*4+2]; ax0 += w.z*v.x; ax1 += w.z*v.y; ax2 += w.z*v.z; ax3 += w.z*v.w;
        v = X4[jb*4+3]; ax0 += w.w*v.x; ax1 += w.w*v.y; ax2 += w.w*v.z; ax3 += w.w*v.w;
      }
      float bhv = s->bhh[g];
      float ah0 = bhv, ah1 = bhv, ah2 = bhv, ah3 = bhv;
      #pragma unroll
      for (int kb = 0; kb < 25; kb++) {
        float4 w = Wh4[kb*300 + g];
        float4 v;
        v = H4[kb*4+0]; ah0 += w.x*v.x; ah1 += w.x*v.y; ah2 += w.x*v.z; ah3 += w.x*v.w;
        v = H4[kb*4+1]; ah0 += w.y*v.x; ah1 += w.y*v.y; ah2 += w.y*v.z; ah3 += w.y*v.w;
        v = H4[kb*4+2]; ah0 += w.z*v.x; ah1 += w.z*v.y; ah2 += w.z*v.z; ah3 += w.z*v.w;
        v = H4[kb*4+3]; ah0 += w.w*v.x; ah1 += w.w*v.y; ah2 += w.w*v.z; ah3 += w.w*v.w;
      }
      s->xp[0*300+g] = ax0; s->xp[1*300+g] = ax1; s->xp[2*300+g] = ax2; s->xp[3*300+g] = ax3;
      s->gh[0*300+g] = ah0; s->gh[1*300+g] = ah1; s->gh[2*300+g] = ah2; s->gh[3*300+g] = ah3;
    }
    __syncthreads();

    for (int idx = tid; idx < 400; idx += NTHR) {   // GRU elementwise + h-freeze
      int e = idx & 3, k = idx >> 2;
      if (step < s->len[e] || step >= maxlen) {
        float ri = s->xp[e*300 + k],       rh = s->gh[e*300 + k];
        float zi = s->xp[e*300 + k + 100], zh = s->gh[e*300 + k + 100];
        float ni = s->xp[e*300 + k + 200], nh = s->gh[e*300 + k + 200];
        float r  = sigmf(ri + rh);
        float zz = sigmf(zi + zh);
        float n  = tanh_fast(ni + r*nh);
        float hv = s->hP[k*4 + e];
        s->hP[k*4 + e] = n + zz*(hv - n);
      }
    }
    __syncthreads();
  }
  zgemm(s, tid, b0, TSTEPS, out);   // final z_{T} from h_{T}
}

extern "C" void kernel_launch(void* const* d_in, const int* in_sizes, int n_in,
                              void* d_out, int out_size) {
  // inputs: context, context_lengths, [t_steps scalar?], W_embed, b_embed,
  //         then W_ih/b_ih/W_hh/b_hh (order auto-detected), W_proj, b_proj
  int off = 2;
  if (n_in >= 11 && in_sizes[2] == 1) off = 3;

  const float* ctx     = (const float*)d_in[0];
  const int*   lens    = (const int*)  d_in[1];
  const float* W_embed = (const float*)d_in[off+0];
  const float* b_embed = (const float*)d_in[off+1];
  const float *W_ih, *b_ih, *W_hh, *b_hh;
  if (in_sizes[off+3] == 3*HDIM) {   // dict order: W_ih, b_ih, W_hh, b_hh
    W_ih = (const float*)d_in[off+2]; b_ih = (const float*)d_in[off+3];
    W_hh = (const float*)d_in[off+4]; b_hh = (const float*)d_in[off+5];
  } else {                           // signature order: W_ih, W_hh, b_ih, b_hh
    W_ih = (const float*)d_in[off+2]; W_hh = (const float*)d_in[off+3];
    b_ih = (const float*)d_in[off+4]; b_hh = (const float*)d_in[off+5];
  }
  const float* W_proj = (const float*)d_in[off+6];
  const float* b_proj = (const float*)d_in[off+7];
  float* out = (float*)d_out;

  prep_kernel<<<219, 256>>>(W_embed, b_embed, W_ih, b_ih, W_hh, W_proj);

  size_t smem_bytes = sizeof(SmemT);
  cudaFuncSetAttribute(rnn_kernel, cudaFuncAttributeMaxDynamicSharedMemorySize,
                       (int)smem_bytes);
  rnn_kernel<<<NBLK, NTHR, smem_bytes>>>(ctx, lens, b_hh, b_proj, out);
}

// round 3
// speedup vs baseline: 1.4250x; 1.4250x over previous
#include <cuda_runtime.h>
#include <cstdint>
#include <cstddef>

#define B_TOT  512
#define LC_    512
#define IDIM   64
#define HDIM   100
#define ODIM   64
#define TSTEPS 256
#define NBLK   128     // 4 examples per CTA
#define NTHR   608     // 19 warps
#define NW     600     // GEMM workers: gate g = w%300, k-half = w/300

typedef unsigned long long u64;

// Packed weights (filled by prep_kernel):
// WcP  : [jb=16][g=300][jj=4] = W_c[g][4*jb+jj]   (W_c = W_ih @ W_embed, 300x64)
// WhhP : [kb=25][g=300][kk=4] = W_hh[g][4*kb+kk]  (300x100)
// WprojP:[kb=25][o= 64][kk=4] = W_proj[o][4*kb+kk](64x100)
__device__ float g_WcP   [16*300*4];
__device__ float g_WhhP  [25*300*4];
__device__ float g_WprojP[25*64*4];
__device__ float g_bc    [300];

__global__ void prep_kernel(const float* __restrict__ W_embed,
                            const float* __restrict__ b_embed,
                            const float* __restrict__ W_ih,
                            const float* __restrict__ b_ih,
                            const float* __restrict__ W_hh,
                            const float* __restrict__ W_proj) {
  int idx = blockIdx.x * 256 + threadIdx.x;
  if (idx < 19200) {                       // W_c = W_ih(300x100) @ W_embed(100x64)
    int g = idx >> 6, j = idx & 63;
    float acc = 0.f;
    #pragma unroll 4
    for (int k = 0; k < 100; k++) acc += W_ih[g*100+k] * W_embed[k*64+j];
    g_WcP[(j>>2)*1200 + g*4 + (j&3)] = acc;
  } else if (idx < 49200) {                // repack W_hh
    int i = idx - 19200, g = i/100, k = i%100;
    g_WhhP[(k>>2)*1200 + g*4 + (k&3)] = W_hh[g*100+k];
  } else if (idx < 55600) {                // repack W_proj
    int i = idx - 49200, o = i/100, k = i%100;
    g_WprojP[(k>>2)*256 + o*4 + (k&3)] = W_proj[o*100+k];
  } else if (idx < 55900) {                // b_c = W_ih @ b_embed + b_ih
    int g = idx - 55600;
    float acc = b_ih[g];
    for (int k = 0; k < 100; k++) acc += W_ih[g*100+k] * b_embed[k];
    g_bc[g] = acc;
  }
}

struct SmemT {
  float WcP [16*300*4];   // 76800 B (re-read per step; W_hh lives in registers)
  float xpH [2][300*4];   // x-gate partials per k-half, layout [g][e]
  float ghH [2][300*4];   // h-gate partials per k-half, layout [g][e]
  float xinP[64*4];       // input vec packed [j][e]
  float hP  [100*4];      // hidden packed [k][e]
  float bproj[64];
  int   len [4];
};                         // ~98.9 KB

// ---- f32x2 helpers (packed fp32 FMA: 2x fma-pipe throughput) ----
__device__ __forceinline__ u64 dup2(float a) {
  u64 r; asm("mov.b64 %0, {%1, %1};" : "=l"(r) : "f"(a)); return r;
}
__device__ __forceinline__ u64 pk2(float a, float b) {
  u64 r; asm("mov.b64 %0, {%1, %2};" : "=l"(r) : "f"(a), "f"(b)); return r;
}
__device__ __forceinline__ void fma2(u64& d, u64 a, u64 b) {
  asm("fma.rn.f32x2 %0, %1, %2, %0;" : "+l"(d) : "l"(a), "l"(b));
}

__device__ __forceinline__ float sigmf(float x) {
  return __fdividef(1.f, 1.f + __expf(-x));
}
__device__ __forceinline__ float tanh_fast(float x) {
  return __fdividef(2.f, 1.f + __expf(-2.f * x)) - 1.f;
}

// z[e][o] = b_proj[o] + h[e] . W_proj[o]; writes d_out and stages z into xinP
__device__ __forceinline__ void zgemm(SmemT* s, int tid, int b0, int tt,
                                      float* __restrict__ out) {
  if (tid < 256) {
    int e = tid >> 6, o = tid & 63;    // warp shares e -> hP loads broadcast
    const float4* Wp4 = reinterpret_cast<const float4*>(g_WprojP);
    float acc = s->bproj[o];
    #pragma unroll
    for (int kb = 0; kb < 25; kb++) {
      float4 w = __ldg(&Wp4[kb*64 + o]);
      acc += w.x * s->hP[(kb*4+0)*4 + e];
      acc += w.y * s->hP[(kb*4+1)*4 + e];
      acc += w.z * s->hP[(kb*4+2)*4 + e];
      acc += w.w * s->hP[(kb*4+3)*4 + e];
    }
    out[((size_t)(b0+e)*(TSTEPS+1) + tt)*ODIM + o] = acc;
    s->xinP[o*4 + e] = acc;
  }
}

__global__ __launch_bounds__(NTHR, 1)
void rnn_kernel(const float* __restrict__ ctx,
                const int*   __restrict__ lens,
                const float* __restrict__ bhh_g,
                const float* __restrict__ bproj_g,
                float*       __restrict__ out) {
  extern __shared__ char smem_raw[];
  SmemT* s = reinterpret_cast<SmemT*>(smem_raw);
  const int tid = threadIdx.x;
  const int b0  = blockIdx.x << 2;

  // ---- prologue ----
  {
    const float4* src = reinterpret_cast<const float4*>(g_WcP);
    float4* dst = reinterpret_cast<float4*>(s->WcP);
    for (int i = tid; i < 16*300; i += NTHR) dst[i] = src[i];
  }
  if (tid < 64)  s->bproj[tid] = bproj_g[tid];
  if (tid < 4)   s->len[tid] = lens[b0 + tid];
  for (int i = tid; i < 400; i += NTHR) s->hP[i] = 0.f;

  // per-worker identity + register-resident W_hh slice
  const int g   = (tid < NW) ? (tid % 300) : 0;
  const int hf  = (tid < NW) ? (tid / 300) : 0;
  const int kb0 = hf ? 12 : 0;
  const int nkb = hf ? 13 : 12;
  const int hf8 = hf * 8;
  float4 whh[13];
  float bias_c = 0.f, bias_h = 0.f;
  if (tid < NW) {
    const float4* Wh4g = reinterpret_cast<const float4*>(g_WhhP);
    #pragma unroll
    for (int i = 0; i < 13; i++)
      if (i < nkb) whh[i] = Wh4g[(kb0 + i)*300 + g];
    if (hf == 0) { bias_c = g_bc[g]; bias_h = bhh_g[g]; }
  }
  __syncthreads();

  int maxlen = max(max(s->len[0], s->len[1]), max(s->len[2], s->len[3]));
  if (maxlen > LC_) maxlen = LC_;

  const float4* Wc4 = reinterpret_cast<const float4*>(s->WcP);
  const float4* X4  = reinterpret_cast<const float4*>(s->xinP);
  const float4* H4  = reinterpret_cast<const float4*>(s->hP);

  // ctx prefetch registers (threads 0..255 stage xinP during encode)
  const int e_s = tid >> 6, j_s = tid & 63;
  const float* ctx_base = ctx + (size_t)(b0 + e_s) * LC_ * IDIM + j_s;
  float creg = 0.f;
  if (tid < 256) creg = ctx_base[0];

  const int total = maxlen + TSTEPS;
  for (int step = 0; step < total; step++) {
    const bool enc = (step < maxlen);

    // ---- phase A: stage input (ctx STS or zgemm) + gh partial (reg weights) ----
    if (enc) {
      if (tid < 256) {
        s->xinP[j_s*4 + e_s] = creg;
        if (step + 1 < maxlen) creg = ctx_base[(size_t)(step+1) * IDIM];
      }
    } else {
      zgemm(s, tid, b0, step - maxlen, out);
    }
    if (tid < NW) {
      u64 ah01 = dup2(bias_h), ah23 = ah01;
      #pragma unroll
      for (int i = 0; i < 13; i++) {
        if (i < nkb) {
          float4 w = whh[i];
          const float4* Hb = H4 + (kb0 + i)*4;
          float4 v;
          u64 wd;
          v = Hb[0]; wd = dup2(w.x); fma2(ah01, wd, pk2(v.x,v.y)); fma2(ah23, wd, pk2(v.z,v.w));
          v = Hb[1]; wd = dup2(w.y); fma2(ah01, wd, pk2(v.x,v.y)); fma2(ah23, wd, pk2(v.z,v.w));
          v = Hb[2]; wd = dup2(w.z); fma2(ah01, wd, pk2(v.x,v.y)); fma2(ah23, wd, pk2(v.z,v.w));
          v = Hb[3]; wd = dup2(w.w); fma2(ah01, wd, pk2(v.x,v.y)); fma2(ah23, wd, pk2(v.z,v.w));
        }
      }
      *reinterpret_cast<u64*>(&s->ghH[hf][g*4 + 0]) = ah01;
      *reinterpret_cast<u64*>(&s->ghH[hf][g*4 + 2]) = ah23;
    }
    __syncthreads();

    // ---- phase B: xp partial from xinP (Wc from smem) ----
    if (tid < NW) {
      u64 ax01 = dup2(bias_c), ax23 = ax01;
      #pragma unroll
      for (int j8 = 0; j8 < 8; j8++) {
        const int jb = hf8 + j8;
        float4 w = Wc4[jb*300 + g];
        const float4* Xb = X4 + jb*4;
        float4 v;
        u64 wd;
        v = Xb[0]; wd = dup2(w.x); fma2(ax01, wd, pk2(v.x,v.y)); fma2(ax23, wd, pk2(v.z,v.w));
        v = Xb[1]; wd = dup2(w.y); fma2(ax01, wd, pk2(v.x,v.y)); fma2(ax23, wd, pk2(v.z,v.w));
        v = Xb[2]; wd = dup2(w.z); fma2(ax01, wd, pk2(v.x,v.y)); fma2(ax23, wd, pk2(v.z,v.w));
        v = Xb[3]; wd = dup2(w.w); fma2(ax01, wd, pk2(v.x,v.y)); fma2(ax23, wd, pk2(v.z,v.w));
      }
      *reinterpret_cast<u64*>(&s->xpH[hf][g*4 + 0]) = ax01;
      *reinterpret_cast<u64*>(&s->xpH[hf][g*4 + 2]) = ax23;
    }
    __syncthreads();

    // ---- phase C: GRU elementwise (sums the two k-half partials) + h-freeze ----
    if (tid < 400) {
      const int e = tid & 3, k = tid >> 2;
      if (enc ? (step < s->len[e]) : true) {
        float ri = s->xpH[0][ k       *4+e] + s->xpH[1][ k       *4+e];
        float rh = s->ghH[0][ k       *4+e] + s->ghH[1][ k       *4+e];
        float zi = s->xpH[0][(k+100)*4+e] + s->xpH[1][(k+100)*4+e];
        float zh = s->ghH[0][(k+100)*4+e] + s->ghH[1][(k+100)*4+e];
        float ni = s->xpH[0][(k+200)*4+e] + s->xpH[1][(k+200)*4+e];
        float nh = s->ghH[0][(k+200)*4+e] + s->ghH[1][(k+200)*4+e];
        float r  = sigmf(ri + rh);
        float zz = sigmf(zi + zh);
        float n  = tanh_fast(ni + r*nh);
        float hv = s->hP[k*4 + e];
        s->hP[k*4 + e] = n + zz*(hv - n);
      }
    }
    __syncthreads();
  }
  zgemm(s, tid, b0, TSTEPS, out);   // final z_T from h_T
}

extern "C" void kernel_launch(void* const* d_in, const int* in_sizes, int n_in,
                              void* d_out, int out_size) {
  int off = 2;
  if (n_in >= 11 && in_sizes[2] == 1) off = 3;

  const float* ctx     = (const float*)d_in[0];
  const int*   lens    = (const int*)  d_in[1];
  const float* W_embed = (const float*)d_in[off+0];
  const float* b_embed = (const float*)d_in[off+1];
  const float *W_ih, *b_ih, *W_hh, *b_hh;
  if (in_sizes[off+3] == 3*HDIM) {   // dict order: W_ih, b_ih, W_hh, b_hh
    W_ih = (const float*)d_in[off+2]; b_ih = (const float*)d_in[off+3];
    W_hh = (const float*)d_in[off+4]; b_hh = (const float*)d_in[off+5];
  } else {                           // signature order: W_ih, W_hh, b_ih, b_hh
    W_ih = (const float*)d_in[off+2]; W_hh = (const float*)d_in[off+3];
    b_ih = (const float*)d_in[off+4]; b_hh = (const float*)d_in[off+5];
  }
  const float* W_proj = (const float*)d_in[off+6];
  const float* b_proj = (const float*)d_in[off+7];
  float* out = (float*)d_out;

  prep_kernel<<<219, 256>>>(W_embed, b_embed, W_ih, b_ih, W_hh, W_proj);

  size_t smem_bytes = sizeof(SmemT);
  cudaFuncSetAttribute(rnn_kernel, cudaFuncAttributeMaxDynamicSharedMemorySize,
                       (int)smem_bytes);
  rnn_kernel<<<NBLK, NTHR, smem_bytes>>>(ctx, lens, b_hh, b_proj, out);
}

// round 4
// speedup vs baseline: 1.4664x; 1.0290x over previous
#include <cuda_runtime.h>
#include <cstdint>
#include <cstddef>

#define B_TOT  512
#define LC_    512
#define IDIM   64
#define HDIM   100
#define ODIM   64
#define TSTEPS 256
#define NBLK   128     // 4 examples per CTA
#define NTHR   608     // 19 warps
#define NW     600     // GEMM workers: g = w%300, k-half hf = w/300

typedef unsigned long long u64;

// ---------------- packed weights (device globals) ----------------
// WcP   : [jb=16][g=300][jj=4] = W_c[g][4*jb+jj]          (W_c = W_ih@W_embed, 300x64)
// WhhP2 : [hf=2][i=13][g=300][kk=4] = W_hh[g][hf*52+4i+kk] (k padded 100->104, pad=0)
// WdP2  : same packing for W_d = W_c @ W_proj (300x100, padded)
// WprojP: [kb=25][o=64][kk=4] = W_proj[o][4*kb+kk]
__device__ float g_WcP   [16*300*4];
__device__ float g_WhhP2 [2*13*300*4];
__device__ float g_WdP2  [2*13*300*4];
__device__ float g_WprojP[25*64*4];
__device__ float g_Wc    [300*64];
__device__ float g_bc    [300];
__device__ float g_bd    [300];

__global__ void prep1(const float* __restrict__ W_embed,
                      const float* __restrict__ b_embed,
                      const float* __restrict__ W_ih,
                      const float* __restrict__ b_ih,
                      const float* __restrict__ W_hh,
                      const float* __restrict__ W_proj) {
  int idx = blockIdx.x * 256 + threadIdx.x;
  if (idx < 19200) {                         // W_c
    int g = idx >> 6, j = idx & 63;
    float acc = 0.f;
    #pragma unroll 4
    for (int k = 0; k < 100; k++) acc += W_ih[g*100+k] * W_embed[k*64+j];
    g_WcP[(j>>2)*1200 + g*4 + (j&3)] = acc;
    g_Wc[g*64 + j] = acc;
  } else if (idx < 19200 + 31200) {          // WhhP2 (padded 13/13 split)
    int i2 = idx - 19200;
    int kh = i2 / 300, g = i2 % 300;         // kh = 0..103
    int hf = kh / 52, rem = kh % 52, i = rem >> 2, kk = rem & 3;
    float v = (kh < 100) ? W_hh[g*100 + kh] : 0.f;
    g_WhhP2[((hf*13 + i)*300 + g)*4 + kk] = v;
  } else if (idx < 19200 + 31200 + 6400) {   // WprojP
    int i2 = idx - 50400, o = i2 / 100, k = i2 % 100;
    g_WprojP[(k>>2)*256 + o*4 + (k&3)] = W_proj[o*100+k];
  } else if (idx < 19200 + 31200 + 6400 + 300) {  // b_c
    int g = idx - 56800;
    float acc = b_ih[g];
    for (int k = 0; k < 100; k++) acc += W_ih[g*100+k] * b_embed[k];
    g_bc[g] = acc;
  }
}

__global__ void prep2(const float* __restrict__ W_proj,
                      const float* __restrict__ b_proj) {
  int idx = blockIdx.x * 256 + threadIdx.x;
  if (idx < 31200) {                         // W_d = W_c @ W_proj (padded packing)
    int kh = idx / 300, g = idx % 300;
    int hf = kh / 52, rem = kh % 52, i = rem >> 2, kk = rem & 3;
    float acc = 0.f;
    if (kh < 100) {
      #pragma unroll 4
      for (int j = 0; j < 64; j++) acc += g_Wc[g*64+j] * W_proj[j*100 + kh];
    }
    g_WdP2[((hf*13 + i)*300 + g)*4 + kk] = acc;
  } else if (idx < 31500) {                  // b_d = W_c @ b_proj + b_c
    int g = idx - 31200;
    float acc = g_bc[g];
    #pragma unroll 4
    for (int j = 0; j < 64; j++) acc += g_Wc[g*64+j] * b_proj[j];
    g_bd[g] = acc;
  }
}

// ---------------- shared layout (byte offsets, 16B aligned) ----------------
// UNION @0 (124800 B): encode = { WcP@0 (76800), xinP@76800 (2048 = [2][256]f) }
//                      decode = WdP2 (124800)
#define OFF_UNION 0
#define OFF_XIN   76800
#define OFF_GHH   124800   // [hf][1200]f = 9600 B
#define OFF_XPH   134400   // 9600 B
#define OFF_HP    144000   // 104 float4 = 1664 B
#define OFF_HT    145664   // [e=4][100]f = 1600 B
#define OFF_BPROJ 147264   // 256 B
#define OFF_LEN   147520   // 16 B
#define SMEM_SZ   147536

// ---------------- f32x2 helpers ----------------
__device__ __forceinline__ u64 dup2(float a) {
  u64 r; asm("mov.b64 %0, {%1, %1};" : "=l"(r) : "f"(a)); return r;
}
__device__ __forceinline__ u64 pk2(float a, float b) {
  u64 r; asm("mov.b64 %0, {%1, %2};" : "=l"(r) : "f"(a), "f"(b)); return r;
}
__device__ __forceinline__ void fma2(u64& d, u64 a, u64 b) {
  asm("fma.rn.f32x2 %0, %1, %2, %0;" : "+l"(d) : "l"(a), "l"(b));
}
__device__ __forceinline__ float2 unpk2(u64 a) {
  float2 f; asm("mov.b64 {%0, %1}, %2;" : "=f"(f.x), "=f"(f.y) : "l"(a)); return f;
}

__device__ __forceinline__ float sigmf(float x) {
  return __fdividef(1.f, 1.f + __expf(-x));
}
__device__ __forceinline__ float tanh_fast(float x) {
  return __fdividef(2.f, 1.f + __expf(-2.f * x)) - 1.f;
}

// z[e][o] = b_proj[o] + h[e].W_proj[o]; reads transposed hT, writes d_out
__device__ __forceinline__ void zgemm(char* sm, int tid, int b0, int tt,
                                      float* __restrict__ out) {
  if (tid < 256) {
    const int e = tid >> 6, o = tid & 63;
    const float4* hT4 = reinterpret_cast<const float4*>(sm + OFF_HT + e*400);
    const float4* Wp4 = reinterpret_cast<const float4*>(g_WprojP);
    float acc = reinterpret_cast<const float*>(sm + OFF_BPROJ)[o];
    #pragma unroll
    for (int kb = 0; kb < 25; kb++) {
      float4 w = __ldg(&Wp4[kb*64 + o]);
      float4 hv = hT4[kb];
      acc += w.x*hv.x + w.y*hv.y + w.z*hv.z + w.w*hv.w;
    }
    out[((size_t)(b0+e)*(TSTEPS+1) + tt)*ODIM + o] = acc;
  }
}

__global__ __launch_bounds__(NTHR, 1)
void rnn_kernel(const float* __restrict__ ctx,
                const int*   __restrict__ lens,
                const float* __restrict__ bhh_g,
                const float* __restrict__ bproj_g,
                float*       __restrict__ out) {
  extern __shared__ char sm[];
  const int tid = threadIdx.x;
  const int b0  = blockIdx.x << 2;

  float* xinP = reinterpret_cast<float*>(sm + OFF_XIN);
  float4* ghH4 = reinterpret_cast<float4*>(sm + OFF_GHH);   // [hf*300 + g]
  float4* xpH4 = reinterpret_cast<float4*>(sm + OFF_XPH);
  float4* H4   = reinterpret_cast<float4*>(sm + OFF_HP);    // [k] -> 4 e's
  float*  hT   = reinterpret_cast<float*>(sm + OFF_HT);
  int*    lenS = reinterpret_cast<int*>(sm + OFF_LEN);

  // ---- prologue: stage WcP, biases, zero h ----
  {
    const float4* src = reinterpret_cast<const float4*>(g_WcP);
    float4* dst = reinterpret_cast<float4*>(sm + OFF_UNION);
    for (int i = tid; i < 4800; i += NTHR) dst[i] = src[i];
  }
  if (tid < 64) reinterpret_cast<float*>(sm + OFF_BPROJ)[tid] = bproj_g[tid];
  if (tid < 4)  lenS[tid] = lens[b0 + tid];
  for (int i = tid; i < 104; i += NTHR) H4[i] = make_float4(0.f,0.f,0.f,0.f);
  for (int i = tid; i < 400; i += NTHR) hT[i] = 0.f;

  const int g  = (tid < NW) ? (tid % 300) : 0;
  const int hf = (tid < NW) ? (tid / 300) : 0;
  const int hf8 = hf * 8;
  float4 wh[13];
  float bias_h = 0.f, bias_c = 0.f, bias_d = 0.f;
  if (tid < NW) {
    const float4* Wh4g = reinterpret_cast<const float4*>(g_WhhP2);
    #pragma unroll
    for (int i = 0; i < 13; i++) wh[i] = Wh4g[(hf*13 + i)*300 + g];
    if (hf == 0) { bias_h = bhh_g[g]; bias_c = g_bc[g]; bias_d = g_bd[g]; }
  }
  __syncthreads();

  int len0 = lenS[0], len1 = lenS[1], len2 = lenS[2], len3 = lenS[3];
  int maxlen = max(max(len0, len1), max(len2, len3));
  if (maxlen > LC_) maxlen = LC_;

  // ctx staging (threads 0..255)
  const int e_s = tid >> 6, j_s = tid & 63;
  const float* ctx_base = ctx + (size_t)(b0 + e_s) * LC_ * IDIM + j_s;
  float creg = 0.f;
  if (tid < 256) {
    xinP[0*256 + j_s*4 + e_s] = ctx_base[0];
    if (maxlen > 1) creg = ctx_base[IDIM];
  }
  __syncthreads();

  const float4* Wc4 = reinterpret_cast<const float4*>(sm + OFF_UNION);
  const float4* Hb  = H4 + hf*52;

  // ================= ENCODE =================
  for (int t = 0; t < maxlen; t++) {
    // phase AB: gh (whh regs) + xp (Wc smem) + stage xin[t+1]
    if (tid < 256) {
      if (t + 1 < maxlen) {
        xinP[((t+1)&1)*256 + j_s*4 + e_s] = creg;
        if (t + 2 < maxlen) creg = ctx_base[(size_t)(t+2)*IDIM];
      }
    }
    if (tid < NW) {
      const float4* X4 = reinterpret_cast<const float4*>(xinP + (t&1)*256);
      u64 ah01 = dup2(bias_h), ah23 = ah01;
      u64 ax01 = dup2(bias_c), ax23 = ax01;
      #pragma unroll
      for (int i = 0; i < 13; i++) {
        float4 w = wh[i];
        float4 v0 = Hb[i*4+0], v1 = Hb[i*4+1], v2 = Hb[i*4+2], v3 = Hb[i*4+3];
        u64 wd;
        wd = dup2(w.x); fma2(ah01, wd, pk2(v0.x,v0.y)); fma2(ah23, wd, pk2(v0.z,v0.w));
        wd = dup2(w.y); fma2(ah01, wd, pk2(v1.x,v1.y)); fma2(ah23, wd, pk2(v1.z,v1.w));
        wd = dup2(w.z); fma2(ah01, wd, pk2(v2.x,v2.y)); fma2(ah23, wd, pk2(v2.z,v2.w));
        wd = dup2(w.w); fma2(ah01, wd, pk2(v3.x,v3.y)); fma2(ah23, wd, pk2(v3.z,v3.w));
      }
      #pragma unroll
      for (int j8 = 0; j8 < 8; j8++) {
        float4 w = Wc4[(hf8 + j8)*300 + g];
        const float4* Xb = X4 + (hf8 + j8)*4;
        float4 v0 = Xb[0], v1 = Xb[1], v2 = Xb[2], v3 = Xb[3];
        u64 wd;
        wd = dup2(w.x); fma2(ax01, wd, pk2(v0.x,v0.y)); fma2(ax23, wd, pk2(v0.z,v0.w));
        wd = dup2(w.y); fma2(ax01, wd, pk2(v1.x,v1.y)); fma2(ax23, wd, pk2(v1.z,v1.w));
        wd = dup2(w.z); fma2(ax01, wd, pk2(v2.x,v2.y)); fma2(ax23, wd, pk2(v2.z,v2.w));
        wd = dup2(w.w); fma2(ax01, wd, pk2(v3.x,v3.y)); fma2(ax23, wd, pk2(v3.z,v3.w));
      }
      float2 a = unpk2(ah01), b = unpk2(ah23);
      ghH4[hf*300 + g] = make_float4(a.x, a.y, b.x, b.y);
      float2 c = unpk2(ax01), d = unpk2(ax23);
      xpH4[hf*300 + g] = make_float4(c.x, c.y, d.x, d.y);
    }
    __syncthreads();

    // phase C: 100 threads, float4 over e; freeze past len
    if (tid < 100) {
      const int k = tid;
      float4 x0, x1, g0, g1;
      x0 = xpH4[k];       x1 = xpH4[300+k];
      g0 = ghH4[k];       g1 = ghH4[300+k];
      float4 ri = make_float4(x0.x+x1.x, x0.y+x1.y, x0.z+x1.z, x0.w+x1.w);
      float4 rh = make_float4(g0.x+g1.x, g0.y+g1.y, g0.z+g1.z, g0.w+g1.w);
      x0 = xpH4[100+k];   x1 = xpH4[400+k];
      g0 = ghH4[100+k];   g1 = ghH4[400+k];
      float4 zi = make_float4(x0.x+x1.x, x0.y+x1.y, x0.z+x1.z, x0.w+x1.w);
      float4 zh = make_float4(g0.x+g1.x, g0.y+g1.y, g0.z+g1.z, g0.w+g1.w);
      x0 = xpH4[200+k];   x1 = xpH4[500+k];
      g0 = ghH4[200+k];   g1 = ghH4[500+k];
      float4 ni = make_float4(x0.x+x1.x, x0.y+x1.y, x0.z+x1.z, x0.w+x1.w);
      float4 nh = make_float4(g0.x+g1.x, g0.y+g1.y, g0.z+g1.z, g0.w+g1.w);
      float4 ho = H4[k];
      float4 hn;
      { float r = sigmf(ri.x+rh.x), z = sigmf(zi.x+zh.x), n = tanh_fast(ni.x + r*nh.x);
        hn.x = (t < len0) ? (n + z*(ho.x-n)) : ho.x; }
      { float r = sigmf(ri.y+rh.y), z = sigmf(zi.y+zh.y), n = tanh_fast(ni.y + r*nh.y);
        hn.y = (t < len1) ? (n + z*(ho.y-n)) : ho.y; }
      { float r = sigmf(ri.z+rh.z), z = sigmf(zi.z+zh.z), n = tanh_fast(ni.z + r*nh.z);
        hn.z = (t < len2) ? (n + z*(ho.z-n)) : ho.z; }
      { float r = sigmf(ri.w+rh.w), z = sigmf(zi.w+zh.w), n = tanh_fast(ni.w + r*nh.w);
        hn.w = (t < len3) ? (n + z*(ho.w-n)) : ho.w; }
      H4[k] = hn;
      hT[0*100+k] = hn.x; hT[1*100+k] = hn.y; hT[2*100+k] = hn.z; hT[3*100+k] = hn.w;
    }
    __syncthreads();
  }

  // ---- transition: overwrite union with W_d ----
  {
    const float4* src = reinterpret_cast<const float4*>(g_WdP2);
    float4* dst = reinterpret_cast<float4*>(sm + OFF_UNION);
    for (int i = tid; i < 7800; i += NTHR) dst[i] = src[i];
  }
  __syncthreads();
  const float4* Wd4 = reinterpret_cast<const float4*>(sm + OFF_UNION);

  // ================= DECODE =================
  for (int tt = 0; tt < TSTEPS; tt++) {
    // phase AB: z_tt output (from current h) + gh (whh regs) + xp (W_d smem),
    //           gh/xp share the same h loads
    zgemm(sm, tid, b0, tt, out);
    if (tid < NW) {
      u64 ah01 = dup2(bias_h), ah23 = ah01;
      u64 ax01 = dup2(bias_d), ax23 = ax01;
      #pragma unroll
      for (int i = 0; i < 13; i++) {
        float4 w = wh[i];
        float4 wd = Wd4[(hf*13 + i)*300 + g];
        float4 v0 = Hb[i*4+0], v1 = Hb[i*4+1], v2 = Hb[i*4+2], v3 = Hb[i*4+3];
        u64 wq, p01, p23;
        p01 = pk2(v0.x,v0.y); p23 = pk2(v0.z,v0.w);
        wq = dup2(w.x);  fma2(ah01, wq, p01); fma2(ah23, wq, p23);
        wq = dup2(wd.x); fma2(ax01, wq, p01); fma2(ax23, wq, p23);
        p01 = pk2(v1.x,v1.y); p23 = pk2(v1.z,v1.w);
        wq = dup2(w.y);  fma2(ah01, wq, p01); fma2(ah23, wq, p23);
        wq = dup2(wd.y); fma2(ax01, wq, p01); fma2(ax23, wq, p23);
        p01 = pk2(v2.x,v2.y); p23 = pk2(v2.z,v2.w);
        wq = dup2(w.z);  fma2(ah01, wq, p01); fma2(ah23, wq, p23);
        wq = dup2(wd.z); fma2(ax01, wq, p01); fma2(ax23, wq, p23);
        p01 = pk2(v3.x,v3.y); p23 = pk2(v3.z,v3.w);
        wq = dup2(w.w);  fma2(ah01, wq, p01); fma2(ah23, wq, p23);
        wq = dup2(wd.w); fma2(ax01, wq, p01); fma2(ax23, wq, p23);
      }
      float2 a = unpk2(ah01), b = unpk2(ah23);
      ghH4[hf*300 + g] = make_float4(a.x, a.y, b.x, b.y);
      float2 c = unpk2(ax01), d = unpk2(ax23);
      xpH4[hf*300 + g] = make_float4(c.x, c.y, d.x, d.y);
    }
    __syncthreads();

    if (tid < 100) {   // phase C (no freeze)
      const int k = tid;
      float4 x0, x1, g0, g1;
      x0 = xpH4[k];       x1 = xpH4[300+k];
      g0 = ghH4[k];       g1 = ghH4[300+k];
      float4 ri = make_float4(x0.x+x1.x, x0.y+x1.y, x0.z+x1.z, x0.w+x1.w);
      float4 rh = make_float4(g0.x+g1.x, g0.y+g1.y, g0.z+g1.z, g0.w+g1.w);
      x0 = xpH4[100+k];   x1 = xpH4[400+k];
      g0 = ghH4[100+k];   g1 = ghH4[400+k];
      float4 zi = make_float4(x0.x+x1.x, x0.y+x1.y, x0.z+x1.z, x0.w+x1.w);
      float4 zh = make_float4(g0.x+g1.x, g0.y+g1.y, g0.z+g1.z, g0.w+g1.w);
      x0 = xpH4[200+k];   x1 = xpH4[500+k];
      g0 = ghH4[200+k];   g1 = ghH4[500+k];
      float4 ni = make_float4(x0.x+x1.x, x0.y+x1.y, x0.z+x1.z, x0.w+x1.w);
      float4 nh = make_float4(g0.x+g1.x, g0.y+g1.y, g0.z+g1.z, g0.w+g1.w);
      float4 ho = H4[k];
      float4 hn;
      { float r = sigmf(ri.x+rh.x), z = sigmf(zi.x+zh.x), n = tanh_fast(ni.x + r*nh.x);
        hn.x = n + z*(ho.x-n); }
      { float r = sigmf(ri.y+rh.y), z = sigmf(zi.y+zh.y), n = tanh_fast(ni.y + r*nh.y);
        hn.y = n + z*(ho.y-n); }
      { float r = sigmf(ri.z+rh.z), z = sigmf(zi.z+zh.z), n = tanh_fast(ni.z + r*nh.z);
        hn.z = n + z*(ho.z-n); }
      { float r = sigmf(ri.w+rh.w), z = sigmf(zi.w+zh.w), n = tanh_fast(ni.w + r*nh.w);
        hn.w = n + z*(ho.w-n); }
      H4[k] = hn;
      hT[0*100+k] = hn.x; hT[1*100+k] = hn.y; hT[2*100+k] = hn.z; hT[3*100+k] = hn.w;
    }
    __syncthreads();
  }
  zgemm(sm, tid, b0, TSTEPS, out);   // final z_T
}

extern "C" void kernel_launch(void* const* d_in, const int* in_sizes, int n_in,
                              void* d_out, int out_size) {
  int off = 2;
  if (n_in >= 11 && in_sizes[2] == 1) off = 3;

  const float* ctx     = (const float*)d_in[0];
  const int*   lens    = (const int*)  d_in[1];
  const float* W_embed = (const float*)d_in[off+0];
  const float* b_embed = (const float*)d_in[off+1];
  const float *W_ih, *b_ih, *W_hh, *b_hh;
  if (in_sizes[off+3] == 3*HDIM) {   // dict order: W_ih, b_ih, W_hh, b_hh
    W_ih = (const float*)d_in[off+2]; b_ih = (const float*)d_in[off+3];
    W_hh = (const float*)d_in[off+4]; b_hh = (const float*)d_in[off+5];
  } else {                           // signature order: W_ih, W_hh, b_ih, b_hh
    W_ih = (const float*)d_in[off+2]; W_hh = (const float*)d_in[off+3];
    b_ih = (const float*)d_in[off+4]; b_hh = (const float*)d_in[off+5];
  }
  const float* W_proj = (const float*)d_in[off+6];
  const float* b_proj = (const float*)d_in[off+7];
  float* out = (float*)d_out;

  prep1<<<299, 256>>>(W_embed, b_embed, W_ih, b_ih, W_hh, W_proj);
  prep2<<<124, 256>>>(W_proj, b_proj);

  cudaFuncSetAttribute(rnn_kernel, cudaFuncAttributeMaxDynamicSharedMemorySize,
                       SMEM_SZ);
  rnn_kernel<<<NBLK, NTHR, SMEM_SZ>>>(ctx, lens, b_hh, b_proj, out);
}

// round 5
// speedup vs baseline: 1.4710x; 1.0031x over previous
#include <cuda_runtime.h>
#include <cstdint>
#include <cstddef>

#define B_TOT  512
#define LC_    512
#define IDIM   64
#define HDIM   100
#define ODIM   64
#define TSTEPS 256
#define NBLK   128     // 4 examples per CTA
#define NTHR   608     // 19 warps
#define NW     600     // GEMM workers: g = w%300, k-half hf = w/300

typedef unsigned long long u64;

// ---------------- packed weights (device globals) ----------------
// WcP   : [jb=16][g=300][jj=4] = W_c[g][4*jb+jj]          (W_c = W_ih@W_embed, 300x64)
// WhhP2 : [hf=2][i=13][g=300][kk=4] = W_hh[g][hf*52+4i+kk] (k padded 100->104, pad=0)
// WdP2  : same packing for W_d = W_c @ W_proj (300x100, padded)
// WprojP: [kb=25][o=64][kk=4] = W_proj[o][4*kb+kk]
__device__ float g_WcP   [16*300*4];
__device__ float g_WhhP2 [2*13*300*4];
__device__ float g_WdP2  [2*13*300*4];
__device__ float g_WprojP[25*64*4];
__device__ float g_Wc    [300*64];
__device__ float g_bc    [300];
__device__ float g_bd    [300];

__global__ void prep1(const float* __restrict__ W_embed,
                      const float* __restrict__ b_embed,
                      const float* __restrict__ W_ih,
                      const float* __restrict__ b_ih,
                      const float* __restrict__ W_hh,
                      const float* __restrict__ W_proj) {
  int idx = blockIdx.x * 256 + threadIdx.x;
  if (idx < 19200) {                         // W_c
    int g = idx >> 6, j = idx & 63;
    float acc = 0.f;
    #pragma unroll 4
    for (int k = 0; k < 100; k++) acc += W_ih[g*100+k] * W_embed[k*64+j];
    g_WcP[(j>>2)*1200 + g*4 + (j&3)] = acc;
    g_Wc[g*64 + j] = acc;
  } else if (idx < 19200 + 31200) {          // WhhP2 (padded 13/13 split)
    int i2 = idx - 19200;
    int kh = i2 / 300, g = i2 % 300;         // kh = 0..103
    int hf = kh / 52, rem = kh % 52, i = rem >> 2, kk = rem & 3;
    float v = (kh < 100) ? W_hh[g*100 + kh] : 0.f;
    g_WhhP2[((hf*13 + i)*300 + g)*4 + kk] = v;
  } else if (idx < 19200 + 31200 + 6400) {   // WprojP
    int i2 = idx - 50400, o = i2 / 100, k = i2 % 100;
    g_WprojP[(k>>2)*256 + o*4 + (k&3)] = W_proj[o*100+k];
  } else if (idx < 19200 + 31200 + 6400 + 300) {  // b_c
    int g = idx - 56800;
    float acc = b_ih[g];
    for (int k = 0; k < 100; k++) acc += W_ih[g*100+k] * b_embed[k];
    g_bc[g] = acc;
  }
}

__global__ void prep2(const float* __restrict__ W_proj,
                      const float* __restrict__ b_proj) {
  int idx = blockIdx.x * 256 + threadIdx.x;
  if (idx < 31200) {                         // W_d = W_c @ W_proj (padded packing)
    int kh = idx / 300, g = idx % 300;
    int hf = kh / 52, rem = kh % 52, i = rem >> 2, kk = rem & 3;
    float acc = 0.f;
    if (kh < 100) {
      #pragma unroll 4
      for (int j = 0; j < 64; j++) acc += g_Wc[g*64+j] * W_proj[j*100 + kh];
    }
    g_WdP2[((hf*13 + i)*300 + g)*4 + kk] = acc;
  } else if (idx < 31500) {                  // b_d = W_c @ b_proj + b_c
    int g = idx - 31200;
    float acc = g_bc[g];
    #pragma unroll 4
    for (int j = 0; j < 64; j++) acc += g_Wc[g*64+j] * b_proj[j];
    g_bd[g] = acc;
  }
}

// ---------------- shared layout (byte offsets, 16B aligned) ----------------
// UNION @0 (124800 B): encode = { WcP@0 (76800), xinP@76800 (2048 = [2][256]f) }
//                      decode = WdP2 (124800)
#define OFF_UNION 0
#define OFF_XIN   76800
#define OFF_GHH   124800   // [hf][1200]f = 9600 B
#define OFF_XPH   134400   // 9600 B
#define OFF_HP    144000   // 104 float4 = 1664 B
#define OFF_HT    145664   // [e=4][100]f = 1600 B
#define OFF_BPROJ 147264   // 256 B
#define OFF_LEN   147520   // 16 B
#define SMEM_SZ   147536

// ---------------- f32x2 helpers ----------------
__device__ __forceinline__ u64 dup2(float a) {
  u64 r; asm("mov.b64 %0, {%1, %1};" : "=l"(r) : "f"(a)); return r;
}
__device__ __forceinline__ u64 pk2(float a, float b) {
  u64 r; asm("mov.b64 %0, {%1, %2};" : "=l"(r) : "f"(a), "f"(b)); return r;
}
__device__ __forceinline__ void fma2(u64& d, u64 a, u64 b) {
  asm("fma.rn.f32x2 %0, %1, %2, %0;" : "+l"(d) : "l"(a), "l"(b));
}
__device__ __forceinline__ float2 unpk2(u64 a) {
  float2 f; asm("mov.b64 {%0, %1}, %2;" : "=f"(f.x), "=f"(f.y) : "l"(a)); return f;
}

__device__ __forceinline__ float sigmf(float x) {
  return __fdividef(1.f, 1.f + __expf(-x));
}
__device__ __forceinline__ float tanh_fast(float x) {
  return __fdividef(2.f, 1.f + __expf(-2.f * x)) - 1.f;
}

// z[e][o] = b_proj[o] + h[e].W_proj[o]; reads transposed hT, writes d_out
__device__ __forceinline__ void zgemm(char* sm, int tid, int b0, int tt,
                                      float* __restrict__ out) {
  if (tid < 256) {
    const int e = tid >> 6, o = tid & 63;
    const float4* hT4 = reinterpret_cast<const float4*>(sm + OFF_HT + e*400);
    const float4* Wp4 = reinterpret_cast<const float4*>(g_WprojP);
    float acc = reinterpret_cast<const float*>(sm + OFF_BPROJ)[o];
    #pragma unroll
    for (int kb = 0; kb < 25; kb++) {
      float4 w = __ldg(&Wp4[kb*64 + o]);
      float4 hv = hT4[kb];
      acc += w.x*hv.x + w.y*hv.y + w.z*hv.z + w.w*hv.w;
    }
    out[((size_t)(b0+e)*(TSTEPS+1) + tt)*ODIM + o] = acc;
  }
}

__global__ __launch_bounds__(NTHR, 1)
void rnn_kernel(const float* __restrict__ ctx,
                const int*   __restrict__ lens,
                const float* __restrict__ bhh_g,
                const float* __restrict__ bproj_g,
                float*       __restrict__ out) {
  extern __shared__ char sm[];
  const int tid = threadIdx.x;
  const int b0  = blockIdx.x << 2;

  float* xinP = reinterpret_cast<float*>(sm + OFF_XIN);
  float4* ghH4 = reinterpret_cast<float4*>(sm + OFF_GHH);   // [hf*300 + g]
  float4* xpH4 = reinterpret_cast<float4*>(sm + OFF_XPH);
  float4* H4   = reinterpret_cast<float4*>(sm + OFF_HP);    // [k] -> 4 e's
  float*  hT   = reinterpret_cast<float*>(sm + OFF_HT);
  int*    lenS = reinterpret_cast<int*>(sm + OFF_LEN);

  // ---- prologue: stage WcP, biases, zero h ----
  {
    const float4* src = reinterpret_cast<const float4*>(g_WcP);
    float4* dst = reinterpret_cast<float4*>(sm + OFF_UNION);
    for (int i = tid; i < 4800; i += NTHR) dst[i] = src[i];
  }
  if (tid < 64) reinterpret_cast<float*>(sm + OFF_BPROJ)[tid] = bproj_g[tid];
  if (tid < 4)  lenS[tid] = lens[b0 + tid];
  for (int i = tid; i < 104; i += NTHR) H4[i] = make_float4(0.f,0.f,0.f,0.f);
  for (int i = tid; i < 400; i += NTHR) hT[i] = 0.f;

  const int g  = (tid < NW) ? (tid % 300) : 0;
  const int hf = (tid < NW) ? (tid / 300) : 0;
  const int hf8 = hf * 8;
  float4 wh[13];
  float bias_h = 0.f, bias_c = 0.f, bias_d = 0.f;
  if (tid < NW) {
    const float4* Wh4g = reinterpret_cast<const float4*>(g_WhhP2);
    #pragma unroll
    for (int i = 0; i < 13; i++) wh[i] = Wh4g[(hf*13 + i)*300 + g];
    if (hf == 0) { bias_h = bhh_g[g]; bias_c = g_bc[g]; bias_d = g_bd[g]; }
  }
  __syncthreads();

  int len0 = lenS[0], len1 = lenS[1], len2 = lenS[2], len3 = lenS[3];
  int maxlen = max(max(len0, len1), max(len2, len3));
  if (maxlen > LC_) maxlen = LC_;

  // ctx staging (threads 0..255)
  const int e_s = tid >> 6, j_s = tid & 63;
  const float* ctx_base = ctx + (size_t)(b0 + e_s) * LC_ * IDIM + j_s;
  float creg = 0.f;
  if (tid < 256) {
    xinP[0*256 + j_s*4 + e_s] = ctx_base[0];
    if (maxlen > 1) creg = ctx_base[IDIM];
  }
  __syncthreads();

  const float4* Wc4 = reinterpret_cast<const float4*>(sm + OFF_UNION);
  const float4* Hb  = H4 + hf*52;

  // ================= ENCODE =================
  for (int t = 0; t < maxlen; t++) {
    // phase AB: gh (whh regs) + xp (Wc smem) + stage xin[t+1]
    if (tid < 256) {
      if (t + 1 < maxlen) {
        xinP[((t+1)&1)*256 + j_s*4 + e_s] = creg;
        if (t + 2 < maxlen) creg = ctx_base[(size_t)(t+2)*IDIM];
      }
    }
    if (tid < NW) {
      const float4* X4 = reinterpret_cast<const float4*>(xinP + (t&1)*256);
      u64 ah01 = dup2(bias_h), ah23 = ah01;
      u64 ax01 = dup2(bias_c), ax23 = ax01;
      #pragma unroll
      for (int i = 0; i < 13; i++) {
        float4 w = wh[i];
        float4 v0 = Hb[i*4+0], v1 = Hb[i*4+1], v2 = Hb[i*4+2], v3 = Hb[i*4+3];
        u64 wd;
        wd = dup2(w.x); fma2(ah01, wd, pk2(v0.x,v0.y)); fma2(ah23, wd, pk2(v0.z,v0.w));
        wd = dup2(w.y); fma2(ah01, wd, pk2(v1.x,v1.y)); fma2(ah23, wd, pk2(v1.z,v1.w));
        wd = dup2(w.z); fma2(ah01, wd, pk2(v2.x,v2.y)); fma2(ah23, wd, pk2(v2.z,v2.w));
        wd = dup2(w.w); fma2(ah01, wd, pk2(v3.x,v3.y)); fma2(ah23, wd, pk2(v3.z,v3.w));
      }
      #pragma unroll
      for (int j8 = 0; j8 < 8; j8++) {
        float4 w = Wc4[(hf8 + j8)*300 + g];
        const float4* Xb = X4 + (hf8 + j8)*4;
        float4 v0 = Xb[0], v1 = Xb[1], v2 = Xb[2], v3 = Xb[3];
        u64 wd;
        wd = dup2(w.x); fma2(ax01, wd, pk2(v0.x,v0.y)); fma2(ax23, wd, pk2(v0.z,v0.w));
        wd = dup2(w.y); fma2(ax01, wd, pk2(v1.x,v1.y)); fma2(ax23, wd, pk2(v1.z,v1.w));
        wd = dup2(w.z); fma2(ax01, wd, pk2(v2.x,v2.y)); fma2(ax23, wd, pk2(v2.z,v2.w));
        wd = dup2(w.w); fma2(ax01, wd, pk2(v3.x,v3.y)); fma2(ax23, wd, pk2(v3.z,v3.w));
      }
      float2 a = unpk2(ah01), b = unpk2(ah23);
      ghH4[hf*300 + g] = make_float4(a.x, a.y, b.x, b.y);
      float2 c = unpk2(ax01), d = unpk2(ax23);
      xpH4[hf*300 + g] = make_float4(c.x, c.y, d.x, d.y);
    }
    __syncthreads();

    // phase C: 100 threads, float4 over e; freeze past len
    if (tid < 100) {
      const int k = tid;
      float4 x0, x1, g0, g1;
      x0 = xpH4[k];       x1 = xpH4[300+k];
      g0 = ghH4[k];       g1 = ghH4[300+k];
      float4 ri = make_float4(x0.x+x1.x, x0.y+x1.y, x0.z+x1.z, x0.w+x1.w);
      float4 rh = make_float4(g0.x+g1.x, g0.y+g1.y, g0.z+g1.z, g0.w+g1.w);
      x0 = xpH4[100+k];   x1 = xpH4[400+k];
      g0 = ghH4[100+k];   g1 = ghH4[400+k];
      float4 zi = make_float4(x0.x+x1.x, x0.y+x1.y, x0.z+x1.z, x0.w+x1.w);
      float4 zh = make_float4(g0.x+g1.x, g0.y+g1.y, g0.z+g1.z, g0.w+g1.w);
      x0 = xpH4[200+k];   x1 = xpH4[500+k];
      g0 = ghH4[200+k];   g1 = ghH4[500+k];
      float4 ni = make_float4(x0.x+x1.x, x0.y+x1.y, x0.z+x1.z, x0.w+x1.w);
      float4 nh = make_float4(g0.x+g1.x, g0.y+g1.y, g0.z+g1.z, g0.w+g1.w);
      float4 ho = H4[k];
      float4 hn;
      { float r = sigmf(ri.x+rh.x), z = sigmf(zi.x+zh.x), n = tanh_fast(ni.x + r*nh.x);
        hn.x = (t < len0) ? (n + z*(ho.x-n)) : ho.x; }
      { float r = sigmf(ri.y+rh.y), z = sigmf(zi.y+zh.y), n = tanh_fast(ni.y + r*nh.y);
        hn.y = (t < len1) ? (n + z*(ho.y-n)) : ho.y; }
      { float r = sigmf(ri.z+rh.z), z = sigmf(zi.z+zh.z), n = tanh_fast(ni.z + r*nh.z);
        hn.z = (t < len2) ? (n + z*(ho.z-n)) : ho.z; }
      { float r = sigmf(ri.w+rh.w), z = sigmf(zi.w+zh.w), n = tanh_fast(ni.w + r*nh.w);
        hn.w = (t < len3) ? (n + z*(ho.w-n)) : ho.w; }
      H4[k] = hn;
      hT[0*100+k] = hn.x; hT[1*100+k] = hn.y; hT[2*100+k] = hn.z; hT[3*100+k] = hn.w;
    }
    __syncthreads();
  }

  // ---- transition: overwrite union with W_d ----
  {
    const float4* src = reinterpret_cast<const float4*>(g_WdP2);
    float4* dst = reinterpret_cast<float4*>(sm + OFF_UNION);
    for (int i = tid; i < 7800; i += NTHR) dst[i] = src[i];
  }
  __syncthreads();
  const float4* Wd4 = reinterpret_cast<const float4*>(sm + OFF_UNION);

  // ================= DECODE =================
  for (int tt = 0; tt < TSTEPS; tt++) {
    // phase AB: z_tt output (from current h) + gh (whh regs) + xp (W_d smem),
    //           gh/xp share the same h loads
    zgemm(sm, tid, b0, tt, out);
    if (tid < NW) {
      u64 ah01 = dup2(bias_h), ah23 = ah01;
      u64 ax01 = dup2(bias_d), ax23 = ax01;
      #pragma unroll
      for (int i = 0; i < 13; i++) {
        float4 w = wh[i];
        float4 wd = Wd4[(hf*13 + i)*300 + g];
        float4 v0 = Hb[i*4+0], v1 = Hb[i*4+1], v2 = Hb[i*4+2], v3 = Hb[i*4+3];
        u64 wq, p01, p23;
        p01 = pk2(v0.x,v0.y); p23 = pk2(v0.z,v0.w);
        wq = dup2(w.x);  fma2(ah01, wq, p01); fma2(ah23, wq, p23);
        wq = dup2(wd.x); fma2(ax01, wq, p01); fma2(ax23, wq, p23);
        p01 = pk2(v1.x,v1.y); p23 = pk2(v1.z,v1.w);
        wq = dup2(w.y);  fma2(ah01, wq, p01); fma2(ah23, wq, p23);
        wq = dup2(wd.y); fma2(ax01, wq, p01); fma2(ax23, wq, p23);
        p01 = pk2(v2.x,v2.y); p23 = pk2(v2.z,v2.w);
        wq = dup2(w.z);  fma2(ah01, wq, p01); fma2(ah23, wq, p23);
        wq = dup2(wd.z); fma2(ax01, wq, p01); fma2(ax23, wq, p23);
        p01 = pk2(v3.x,v3.y); p23 = pk2(v3.z,v3.w);
        wq = dup2(w.w);  fma2(ah01, wq, p01); fma2(ah23, wq, p23);
        wq = dup2(wd.w); fma2(ax01, wq, p01); fma2(ax23, wq, p23);
      }
      float2 a = unpk2(ah01), b = unpk2(ah23);
      ghH4[hf*300 + g] = make_float4(a.x, a.y, b.x, b.y);
      float2 c = unpk2(ax01), d = unpk2(ax23);
      xpH4[hf*300 + g] = make_float4(c.x, c.y, d.x, d.y);
    }
    __syncthreads();

    if (tid < 100) {   // phase C (no freeze)
      const int k = tid;
      float4 x0, x1, g0, g1;
      x0 = xpH4[k];       x1 = xpH4[300+k];
      g0 = ghH4[k];       g1 = ghH4[300+k];
      float4 ri = make_float4(x0.x+x1.x, x0.y+x1.y, x0.z+x1.z, x0.w+x1.w);
      float4 rh = make_float4(g0.x+g1.x, g0.y+g1.y, g0.z+g1.z, g0.w+g1.w);
      x0 = xpH4[100+k];   x1 = xpH4[400+k];
      g0 = ghH4[100+k];   g1 = ghH4[400+k];
      float4 zi = make_float4(x0.x+x1.x, x0.y+x1.y, x0.z+x1.z, x0.w+x1.w);
      float4 zh = make_float4(g0.x+g1.x, g0.y+g1.y, g0.z+g1.z, g0.w+g1.w);
      x0 = xpH4[200+k];   x1 = xpH4[500+k];
      g0 = ghH4[200+k];   g1 = ghH4[500+k];
      float4 ni = make_float4(x0.x+x1.x, x0.y+x1.y, x0.z+x1.z, x0.w+x1.w);
      float4 nh = make_float4(g0.x+g1.x, g0.y+g1.y, g0.z+g1.z, g0.w+g1.w);
      float4 ho = H4[k];
      float4 hn;
      { float r = sigmf(ri.x+rh.x), z = sigmf(zi.x+zh.x), n = tanh_fast(ni.x + r*nh.x);
        hn.x = n + z*(ho.x-n); }
      { float r = sigmf(ri.y+rh.y), z = sigmf(zi.y+zh.y), n = tanh_fast(ni.y + r*nh.y);
        hn.y = n + z*(ho.y-n); }
      { float r = sigmf(ri.z+rh.z), z = sigmf(zi.z+zh.z), n = tanh_fast(ni.z + r*nh.z);
        hn.z = n + z*(ho.z-n); }
      { float r = sigmf(ri.w+rh.w), z = sigmf(zi.w+zh.w), n = tanh_fast(ni.w + r*nh.w);
        hn.w = n + z*(ho.w-n); }
      H4[k] = hn;
      hT[0*100+k] = hn.x; hT[1*100+k] = hn.y; hT[2*100+k] = hn.z; hT[3*100+k] = hn.w;
    }
    __syncthreads();
  }
  zgemm(sm, tid, b0, TSTEPS, out);   // final z_T
}

extern "C" void kernel_launch(void* const* d_in, const int* in_sizes, int n_in,
                              void* d_out, int out_size) {
  int off = 2;
  if (n_in >= 11 && in_sizes[2] == 1) off = 3;

  const float* ctx     = (const float*)d_in[0];
  const int*   lens    = (const int*)  d_in[1];
  const float* W_embed = (const float*)d_in[off+0];
  const float* b_embed = (const float*)d_in[off+1];
  const float *W_ih, *b_ih, *W_hh, *b_hh;
  if (in_sizes[off+3] == 3*HDIM) {   // dict order: W_ih, b_ih, W_hh, b_hh
    W_ih = (const float*)d_in[off+2]; b_ih = (const float*)d_in[off+3];
    W_hh = (const float*)d_in[off+4]; b_hh = (const float*)d_in[off+5];
  } else {                           // signature order: W_ih, W_hh, b_ih, b_hh
    W_ih = (const float*)d_in[off+2]; W_hh = (const float*)d_in[off+3];
    b_ih = (const float*)d_in[off+4]; b_hh = (const float*)d_in[off+5];
  }
  const float* W_proj = (const float*)d_in[off+6];
  const float* b_proj = (const float*)d_in[off+7];
  float* out = (float*)d_out;

  prep1<<<299, 256>>>(W_embed, b_embed, W_ih, b_ih, W_hh, W_proj);
  prep2<<<124, 256>>>(W_proj, b_proj);

  cudaFuncSetAttribute(rnn_kernel, cudaFuncAttributeMaxDynamicSharedMemorySize,
                       SMEM_SZ);
  rnn_kernel<<<NBLK, NTHR, SMEM_SZ>>>(ctx, lens, b_hh, b_proj, out);
}